// round 4
// baseline (speedup 1.0000x reference)
#include <cuda_runtime.h>
#include <cuda_bf16.h>

#define NN    50000
#define NE    400000
#define INC   128
#define HID   256
#define ED    32

// ---------------- scratch (static device buffers; no allocation) ----------------
__device__ float g_Xs [NN * HID];   // per-node src-side pre-projection
__device__ float g_Xd [NN * HID];   // per-node dst-side pre-projection
__device__ float g_agg[NN * HID];   // mean aggregate
__device__ float g_h  [NN * HID];   // node features (ping)
__device__ float g_h2 [NN * HID];   // node features (pong)
__device__ int   g_degi[NN];        // int degree histogram
__device__ int   g_rowstart[NN + 1];
__device__ int   g_cursor[NN];
__device__ int   g_csr_src[NE];
__device__ int   g_csr_eid[NE];

// ---------------- utility kernels ----------------
__global__ void zero_kernel(float* p, int n4) {
    int i = blockIdx.x * blockDim.x + threadIdx.x;
    if (i < n4) reinterpret_cast<float4*>(p)[i] = make_float4(0.f, 0.f, 0.f, 0.f);
}

__global__ void hist_kernel(const int* __restrict__ dst, int* degi, int E) {
    int e = blockIdx.x * blockDim.x + threadIdx.x;
    if (e < E) atomicAdd(&degi[dst[e]], 1);
}

// single-block exclusive scan over degrees -> rowstart / cursor (1024 threads)
__global__ void scan_kernel(const int* __restrict__ deg,
                            int* __restrict__ rowstart,
                            int* __restrict__ cursor, int n)
{
    __shared__ int wsum[32];
    __shared__ int woff[32];
    __shared__ int carry_s;
    __shared__ int tot_s;
    const int tid = threadIdx.x, lane = tid & 31, wid = tid >> 5;
    if (tid == 0) carry_s = 0;
    __syncthreads();

    for (int base = 0; base < n; base += 1024) {
        int i = base + tid;
        int v = (i < n) ? deg[i] : 0;
        int incl = v;
#pragma unroll
        for (int off = 1; off < 32; off <<= 1) {
            int t = __shfl_up_sync(0xffffffffu, incl, off);
            if (lane >= off) incl += t;
        }
        if (lane == 31) wsum[wid] = incl;
        __syncthreads();
        if (wid == 0) {
            int s = wsum[lane];
            int si = s;
#pragma unroll
            for (int off = 1; off < 32; off <<= 1) {
                int t = __shfl_up_sync(0xffffffffu, si, off);
                if (lane >= off) si += t;
            }
            woff[lane] = si - s;          // exclusive warp offsets
            if (lane == 31) tot_s = si;   // chunk total
        }
        __syncthreads();
        int excl_all = carry_s + woff[wid] + (incl - v);
        if (i < n) { rowstart[i] = excl_all; cursor[i] = excl_all; }
        __syncthreads();
        if (tid == 0) carry_s += tot_s;
        __syncthreads();
    }
    if (tid == 0) rowstart[n] = carry_s;
}

__global__ void scatter_kernel(const int* __restrict__ src, const int* __restrict__ dst,
                               int* __restrict__ cursor,
                               int* __restrict__ csr_src, int* __restrict__ csr_eid, int E)
{
    int e = blockIdx.x * blockDim.x + threadIdx.x;
    if (e < E) {
        int d = dst[e];
        int pos = atomicAdd(&cursor[d], 1);
        csr_src[pos] = src[e];
        csr_eid[pos] = e;
    }
}

// ---------------- fused edge message + mean aggregation (CSR, no atomics) ----------------
// For dst node d: agg[d][j] = (1/max(deg,1)) * sum_{edges e: dst=d}
//                 relu( b[j] + Xs[src_e][j] + Xd[d][j] + sum_k attr[e][k]*We[k][j] )
// Thread j owns channel j; weight column We[:,j] hoisted into registers.
#define AGG_CTAS 888

__global__ __launch_bounds__(256) void agg_kernel(
    const float* __restrict__ Xs, const float* __restrict__ Xd,
    const float* __restrict__ eattr,
    const float* __restrict__ We, const float* __restrict__ bias,
    const int* __restrict__ rowstart,
    const int* __restrict__ csr_src, const int* __restrict__ csr_eid,
    float* __restrict__ agg)
{
    const int j    = threadIdx.x;
    const int lane = j & 31;

    float w[ED];
#pragma unroll
    for (int k = 0; k < ED; k++) w[k] = We[k * HID + j];
    const float bj = bias[j];

    const int per = (NN + gridDim.x - 1) / gridDim.x;
    const int n0  = blockIdx.x * per;
    const int n1  = (n0 + per < NN) ? (n0 + per) : NN;

    for (int d = n0; d < n1; ++d) {
        const int rs = __ldg(&rowstart[d]);
        const int re = __ldg(&rowstart[d + 1]);
        const float xd = Xd[(long)d * HID + j];
        float acc = 0.f;
        for (int p = rs; p < re; ++p) {
            const int s = __ldg(&csr_src[p]);
            const int e = __ldg(&csr_eid[p]);
            const float av = __ldg(&eattr[(long)e * ED + lane]);
            float m = bj + Xs[(long)s * HID + j] + xd;
#pragma unroll
            for (int k = 0; k < ED; k++)
                m = fmaf(__shfl_sync(0xffffffffu, av, k), w[k], m);
            acc += fmaxf(m, 0.f);
        }
        const int  deg = re - rs;
        const float inv = 1.f / (float)((deg > 1) ? deg : 1);
        agg[(long)d * HID + j] = acc * inv;
    }
}

// ---------------- tiled fp32 GEMM: C = act( A1@W1 [+ A2@W2] + bias ) ----------------
#define BM 128
#define BN 128
#define BK 8
#define TM 8
#define TN 8

__global__ __launch_bounds__(256) void gemm_dual_kernel(
    const float* __restrict__ A1, const float* __restrict__ W1, int K1,
    const float* __restrict__ A2, const float* __restrict__ W2, int K2,
    const float* __restrict__ bias, int relu,
    float* __restrict__ C, int M, int N)
{
    __shared__ float As[BK][BM];
    __shared__ float Bs[BK][BN];

    const int bm  = blockIdx.y * BM;
    const int bn  = blockIdx.x * BN;
    const int tid = threadIdx.x;
    const int tr  = tid / (BN / TN);
    const int tc  = tid % (BN / TN);

    float acc[TM][TN];
#pragma unroll
    for (int i = 0; i < TM; i++)
#pragma unroll
        for (int j = 0; j < TN; j++) acc[i][j] = 0.f;

    const int aRow = tid >> 1;
    const int aCol = (tid & 1) * 4;
    const int bRow = tid >> 5;
    const int bCol = (tid & 31) * 4;

    for (int pass = 0; pass < 2; ++pass) {
        const float* A = pass ? A2 : A1;
        const float* W = pass ? W2 : W1;
        const int    K = pass ? K2 : K1;
        if (A == nullptr) continue;

        for (int k0 = 0; k0 < K; k0 += BK) {
            {
                int r = bm + aRow;
                float4 av = make_float4(0.f, 0.f, 0.f, 0.f);
                if (r < M)
                    av = *reinterpret_cast<const float4*>(A + (long)r * K + k0 + aCol);
                As[aCol + 0][aRow] = av.x;
                As[aCol + 1][aRow] = av.y;
                As[aCol + 2][aRow] = av.z;
                As[aCol + 3][aRow] = av.w;
            }
            {
                float4 bv = *reinterpret_cast<const float4*>(W + (long)(k0 + bRow) * N + bn + bCol);
                *reinterpret_cast<float4*>(&Bs[bRow][bCol]) = bv;
            }
            __syncthreads();

#pragma unroll
            for (int k = 0; k < BK; ++k) {
                float4 a0 = *reinterpret_cast<const float4*>(&As[k][tr * TM]);
                float4 a1 = *reinterpret_cast<const float4*>(&As[k][tr * TM + 4]);
                float4 b0 = *reinterpret_cast<const float4*>(&Bs[k][tc * TN]);
                float4 b1 = *reinterpret_cast<const float4*>(&Bs[k][tc * TN + 4]);
                float a[TM] = {a0.x, a0.y, a0.z, a0.w, a1.x, a1.y, a1.z, a1.w};
                float b[TN] = {b0.x, b0.y, b0.z, b0.w, b1.x, b1.y, b1.z, b1.w};
#pragma unroll
                for (int i = 0; i < TM; i++)
#pragma unroll
                    for (int jj = 0; jj < TN; jj++)
                        acc[i][jj] = fmaf(a[i], b[jj], acc[i][jj]);
            }
            __syncthreads();
        }
    }

#pragma unroll
    for (int i = 0; i < TM; i++) {
        int r = bm + tr * TM + i;
        if (r >= M) continue;
#pragma unroll
        for (int j = 0; j < TN; j += 4) {
            int c = bn + tc * TN + j;
            float4 v = make_float4(acc[i][j], acc[i][j + 1], acc[i][j + 2], acc[i][j + 3]);
            if (bias) {
                v.x += bias[c];     v.y += bias[c + 1];
                v.z += bias[c + 2]; v.w += bias[c + 3];
            }
            if (relu) {
                v.x = fmaxf(v.x, 0.f); v.y = fmaxf(v.y, 0.f);
                v.z = fmaxf(v.z, 0.f); v.w = fmaxf(v.w, 0.f);
            }
            *reinterpret_cast<float4*>(C + (long)r * N + c) = v;
        }
    }
}

// ---------------- head: out[n] = dot(relu_feats[n], w2) + b2 ----------------
__global__ void head_out_kernel(const float* __restrict__ T,
                                const float* __restrict__ w2,
                                const float* __restrict__ b2,
                                float* __restrict__ out, int n)
{
    int gw   = (blockIdx.x * blockDim.x + threadIdx.x) >> 5;
    int lane = threadIdx.x & 31;
    if (gw >= n) return;
    const float* t = T + (long)gw * HID;
    float acc = 0.f;
#pragma unroll
    for (int k = lane; k < HID; k += 32) acc = fmaf(t[k], w2[k], acc);
#pragma unroll
    for (int o = 16; o; o >>= 1) acc += __shfl_xor_sync(0xffffffffu, acc, o);
    if (lane == 0) out[gw] = acc + b2[0];
}

// ---------------- host orchestration ----------------
template <typename T>
static T* sym_addr(const void* symbol) {
    void* p = nullptr;
    cudaGetSymbolAddress(&p, symbol);
    return (T*)p;
}

static void run_gemm(const float* A1, const float* W1, int K1,
                     const float* A2, const float* W2, int K2,
                     const float* bias, int relu,
                     float* C, int M, int N, cudaStream_t s)
{
    dim3 grid(N / BN, (M + BM - 1) / BM);
    gemm_dual_kernel<<<grid, 256, 0, s>>>(A1, W1, K1, A2, W2, K2, bias, relu, C, M, N);
}

extern "C" void kernel_launch(void* const* d_in, const int* in_sizes, int n_in,
                              void* d_out, int out_size)
{
    cudaStream_t s = 0;
    const float* x     = (const float*)d_in[0];
    const int*   eidx  = (const int*)  d_in[1];
    const float* eattr = (const float*)d_in[2];
    const float* e0_w  = (const float*)d_in[3];
    const float* e0_b  = (const float*)d_in[4];
    const float* n0_w  = (const float*)d_in[5];
    const float* n0_b  = (const float*)d_in[6];
    const float* e_w   = (const float*)d_in[7];   // [2, 544, 256]
    const float* e_b   = (const float*)d_in[8];   // [2, 256]
    const float* n_w   = (const float*)d_in[9];   // [2, 512, 256]
    const float* n_b   = (const float*)d_in[10];  // [2, 256]
    const float* h1_w  = (const float*)d_in[11];
    const float* h1_b  = (const float*)d_in[12];
    const float* h2_w  = (const float*)d_in[13];
    const float* h2_b  = (const float*)d_in[14];

    const int* src = eidx;
    const int* dst = eidx + NE;

    float* Xs   = sym_addr<float>(g_Xs);
    float* Xd   = sym_addr<float>(g_Xd);
    float* agg  = sym_addr<float>(g_agg);
    float* h    = sym_addr<float>(g_h);
    float* h2   = sym_addr<float>(g_h2);
    int*   degi = sym_addr<int>(g_degi);
    int*   rowS = sym_addr<int>(g_rowstart);
    int*   curS = sym_addr<int>(g_cursor);
    int*   csrS = sym_addr<int>(g_csr_src);
    int*   csrE = sym_addr<int>(g_csr_eid);

    // ---------- CSR build (per launch, deterministic work) ----------
    zero_kernel<<<(NN / 4 + 255) / 256, 256, 0, s>>>((float*)degi, NN / 4);
    hist_kernel<<<(NE + 255) / 256, 256, 0, s>>>(dst, degi, NE);
    scan_kernel<<<1, 1024, 0, s>>>(degi, rowS, curS, NN);
    scatter_kernel<<<(NE + 255) / 256, 256, 0, s>>>(src, dst, curS, csrS, csrE, NE);

    // ---------- layer 0 (C = 128) ----------
    {
        const float* Ws = e0_w;
        const float* Wd = e0_w + (long)INC * HID;
        const float* We = e0_w + (long)2 * INC * HID;
        run_gemm(x, Ws, INC, nullptr, nullptr, 0, nullptr, 0, Xs, NN, HID, s);
        run_gemm(x, Wd, INC, nullptr, nullptr, 0, nullptr, 0, Xd, NN, HID, s);
        agg_kernel<<<AGG_CTAS, 256, 0, s>>>(Xs, Xd, eattr, We, e0_b, rowS, csrS, csrE, agg);
        run_gemm(x, n0_w, INC, agg, n0_w + (long)INC * HID, HID, n0_b, 1, h, NN, HID, s);
    }

    // ---------- layers 1..2 (C = 256) ----------
    float* cur = h;
    float* nxt = h2;
    for (int L = 0; L < 2; ++L) {
        const float* ew = e_w + (long)L * (2 * HID + ED) * HID;
        const float* eb = e_b + (long)L * HID;
        const float* nw = n_w + (long)L * (2 * HID) * HID;
        const float* nb = n_b + (long)L * HID;
        const float* Ws = ew;
        const float* Wd = ew + (long)HID * HID;
        const float* We = ew + (long)2 * HID * HID;

        run_gemm(cur, Ws, HID, nullptr, nullptr, 0, nullptr, 0, Xs, NN, HID, s);
        run_gemm(cur, Wd, HID, nullptr, nullptr, 0, nullptr, 0, Xd, NN, HID, s);
        agg_kernel<<<AGG_CTAS, 256, 0, s>>>(Xs, Xd, eattr, We, eb, rowS, csrS, csrE, agg);
        run_gemm(cur, nw, HID, agg, nw + (long)HID * HID, HID, nb, 1, nxt, NN, HID, s);

        float* t = cur; cur = nxt; nxt = t;
    }

    // ---------- head ----------
    run_gemm(cur, h1_w, HID, nullptr, nullptr, 0, h1_b, 1, nxt, NN, HID, s);
    head_out_kernel<<<(NN * 32 + 255) / 256, 256, 0, s>>>(nxt, h2_w, h2_b, (float*)d_out, NN);
}

// round 5
// speedup vs baseline: 1.2759x; 1.2759x over previous
#include <cuda_runtime.h>
#include <cuda_bf16.h>

#define NN    50000
#define NE    400000
#define INC   128
#define HID   256
#define ED    32

// ---------------- scratch (static device buffers; no allocation) ----------------
__device__ float g_Xs [NN * HID];
__device__ float g_Xd [NN * HID];
__device__ float g_agg[NN * HID];
__device__ float g_h  [NN * HID];
__device__ float g_h2 [NN * HID];
__device__ float g_Ea [NE * HID];    // per-edge We@attr + bias (410 MB)
__device__ int   g_degi[NN];
__device__ int   g_rowstart[NN + 1];
__device__ int   g_cursor[NN];
__device__ int   g_csr_src[NE];
__device__ int   g_csr_eid[NE];

// ---------------- f32x2 packed helpers ----------------
__device__ __forceinline__ unsigned long long pack2(float x, float y) {
    unsigned long long r;
    asm("mov.b64 %0, {%1,%2};" : "=l"(r) : "f"(x), "f"(y));
    return r;
}
__device__ __forceinline__ void unpack2(unsigned long long v, float& x, float& y) {
    asm("mov.b64 {%0,%1}, %2;" : "=f"(x), "=f"(y) : "l"(v));
}
__device__ __forceinline__ void fma2(unsigned long long& d,
                                     unsigned long long a, unsigned long long b) {
    asm("fma.rn.f32x2 %0, %1, %2, %3;" : "=l"(d) : "l"(a), "l"(b), "l"(d));
}

// ---------------- utility kernels ----------------
__global__ void zero_kernel(float* p, int n4) {
    int i = blockIdx.x * blockDim.x + threadIdx.x;
    if (i < n4) reinterpret_cast<float4*>(p)[i] = make_float4(0.f, 0.f, 0.f, 0.f);
}

__global__ void hist_kernel(const int* __restrict__ dst, int* degi, int E) {
    int e = blockIdx.x * blockDim.x + threadIdx.x;
    if (e < E) atomicAdd(&degi[dst[e]], 1);
}

// single-block exclusive scan over degrees -> rowstart / cursor (1024 threads)
__global__ void scan_kernel(const int* __restrict__ deg,
                            int* __restrict__ rowstart,
                            int* __restrict__ cursor, int n)
{
    __shared__ int wsum[32];
    __shared__ int woff[32];
    __shared__ int carry_s;
    __shared__ int tot_s;
    const int tid = threadIdx.x, lane = tid & 31, wid = tid >> 5;
    if (tid == 0) carry_s = 0;
    __syncthreads();

    for (int base = 0; base < n; base += 1024) {
        int i = base + tid;
        int v = (i < n) ? deg[i] : 0;
        int incl = v;
#pragma unroll
        for (int off = 1; off < 32; off <<= 1) {
            int t = __shfl_up_sync(0xffffffffu, incl, off);
            if (lane >= off) incl += t;
        }
        if (lane == 31) wsum[wid] = incl;
        __syncthreads();
        if (wid == 0) {
            int s = wsum[lane];
            int si = s;
#pragma unroll
            for (int off = 1; off < 32; off <<= 1) {
                int t = __shfl_up_sync(0xffffffffu, si, off);
                if (lane >= off) si += t;
            }
            woff[lane] = si - s;
            if (lane == 31) tot_s = si;
        }
        __syncthreads();
        int excl_all = carry_s + woff[wid] + (incl - v);
        if (i < n) { rowstart[i] = excl_all; cursor[i] = excl_all; }
        __syncthreads();
        if (tid == 0) carry_s += tot_s;
        __syncthreads();
    }
    if (tid == 0) rowstart[n] = carry_s;
}

__global__ void scatter_kernel(const int* __restrict__ src, const int* __restrict__ dst,
                               int* __restrict__ cursor,
                               int* __restrict__ csr_src, int* __restrict__ csr_eid, int E)
{
    int e = blockIdx.x * blockDim.x + threadIdx.x;
    if (e < E) {
        int d = dst[e];
        int pos = atomicAdd(&cursor[d], 1);
        csr_src[pos] = src[e];
        csr_eid[pos] = e;
    }
}

// ---------------- CSR mean aggregation: pure streaming adds, no SHFL/atomics ----------------
// agg[d][j] = 1/max(deg,1) * sum_e relu( Xs[src_e][j] + Xd[d][j] + Ea[e][j] )
#define AGG_CTAS 1184

__global__ __launch_bounds__(256) void agg2_kernel(
    const float* __restrict__ Xs, const float* __restrict__ Xd,
    const float* __restrict__ Ea,
    const int* __restrict__ rowstart,
    const int* __restrict__ csr_src, const int* __restrict__ csr_eid,
    float* __restrict__ agg)
{
    const int j = threadIdx.x;
    for (int d = blockIdx.x; d < NN; d += gridDim.x) {
        const int rs = __ldg(&rowstart[d]);
        const int re = __ldg(&rowstart[d + 1]);
        const float xd = Xd[(long)d * HID + j];
        float acc0 = 0.f, acc1 = 0.f;
        int p = rs;
        for (; p + 1 < re; p += 2) {
            const int s0 = __ldg(&csr_src[p]);
            const int e0 = __ldg(&csr_eid[p]);
            const int s1 = __ldg(&csr_src[p + 1]);
            const int e1 = __ldg(&csr_eid[p + 1]);
            const float m0 = __ldg(&Xs[(long)s0 * HID + j]) + __ldg(&Ea[(long)e0 * HID + j]) + xd;
            const float m1 = __ldg(&Xs[(long)s1 * HID + j]) + __ldg(&Ea[(long)e1 * HID + j]) + xd;
            acc0 += fmaxf(m0, 0.f);
            acc1 += fmaxf(m1, 0.f);
        }
        if (p < re) {
            const int s0 = __ldg(&csr_src[p]);
            const int e0 = __ldg(&csr_eid[p]);
            acc0 += fmaxf(__ldg(&Xs[(long)s0 * HID + j]) + __ldg(&Ea[(long)e0 * HID + j]) + xd, 0.f);
        }
        const int  deg = re - rs;
        const float inv = 1.f / (float)((deg > 1) ? deg : 1);
        agg[(long)d * HID + j] = (acc0 + acc1) * inv;
    }
}

// ---------------- tiled fp32 GEMM with packed f32x2 FMA ----------------
// C = act( A1@W1 [+ A2@W2] + bias ). M-paired accumulators: acc2[i2][j] holds
// rows (2*i2, 2*i2+1) of the thread tile packed in one 64-bit register.
#define BM 128
#define BN 128
#define BK 8
#define TM 8
#define TN 8

__global__ __launch_bounds__(256) void gemm_dual_kernel(
    const float* __restrict__ A1, const float* __restrict__ W1, int K1,
    const float* __restrict__ A2, const float* __restrict__ W2, int K2,
    const float* __restrict__ bias, int relu,
    float* __restrict__ C, int M, int N)
{
    __shared__ float As[BK][BM];
    __shared__ float Bs[BK][BN];

    const int bm  = blockIdx.y * BM;
    const int bn  = blockIdx.x * BN;
    const int tid = threadIdx.x;
    const int tr  = tid / (BN / TN);
    const int tc  = tid % (BN / TN);

    unsigned long long acc2[TM / 2][TN];
#pragma unroll
    for (int i = 0; i < TM / 2; i++)
#pragma unroll
        for (int j = 0; j < TN; j++) acc2[i][j] = 0ull;

    const int aRow = tid >> 1;
    const int aCol = (tid & 1) * 4;
    const int bRow = tid >> 5;
    const int bCol = (tid & 31) * 4;

    for (int pass = 0; pass < 2; ++pass) {
        const float* A = pass ? A2 : A1;
        const float* W = pass ? W2 : W1;
        const int    K = pass ? K2 : K1;
        if (A == nullptr) continue;

        for (int k0 = 0; k0 < K; k0 += BK) {
            {
                int r = bm + aRow;
                float4 av = make_float4(0.f, 0.f, 0.f, 0.f);
                if (r < M)
                    av = *reinterpret_cast<const float4*>(A + (long)r * K + k0 + aCol);
                As[aCol + 0][aRow] = av.x;
                As[aCol + 1][aRow] = av.y;
                As[aCol + 2][aRow] = av.z;
                As[aCol + 3][aRow] = av.w;
            }
            {
                float4 bv = *reinterpret_cast<const float4*>(W + (long)(k0 + bRow) * N + bn + bCol);
                *reinterpret_cast<float4*>(&Bs[bRow][bCol]) = bv;
            }
            __syncthreads();

#pragma unroll
            for (int k = 0; k < BK; ++k) {
                // a: 4 packed pairs of adjacent M-rows (direct 64-bit smem loads)
                unsigned long long aa[TM / 2];
#pragma unroll
                for (int i = 0; i < TM / 2; i++)
                    aa[i] = *reinterpret_cast<const unsigned long long*>(&As[k][tr * TM + 2 * i]);
                // b: 8 scalars, duplicated into both packed halves
                float4 b0 = *reinterpret_cast<const float4*>(&Bs[k][tc * TN]);
                float4 b1 = *reinterpret_cast<const float4*>(&Bs[k][tc * TN + 4]);
                unsigned long long bb[TN];
                bb[0] = pack2(b0.x, b0.x); bb[1] = pack2(b0.y, b0.y);
                bb[2] = pack2(b0.z, b0.z); bb[3] = pack2(b0.w, b0.w);
                bb[4] = pack2(b1.x, b1.x); bb[5] = pack2(b1.y, b1.y);
                bb[6] = pack2(b1.z, b1.z); bb[7] = pack2(b1.w, b1.w);
#pragma unroll
                for (int i = 0; i < TM / 2; i++)
#pragma unroll
                    for (int j = 0; j < TN; j++)
                        fma2(acc2[i][j], aa[i], bb[j]);
            }
            __syncthreads();
        }
    }

    // epilogue: unpack pairs, apply bias/relu, vectorized store
#pragma unroll
    for (int i = 0; i < TM / 2; i++) {
        float row0[TN], row1[TN];
#pragma unroll
        for (int j = 0; j < TN; j++) unpack2(acc2[i][j], row0[j], row1[j]);

#pragma unroll
        for (int half = 0; half < 2; half++) {
            int r = bm + tr * TM + 2 * i + half;
            if (r >= M) continue;
            float* rowv = half ? row1 : row0;
#pragma unroll
            for (int j = 0; j < TN; j += 4) {
                int c = bn + tc * TN + j;
                float4 v = make_float4(rowv[j], rowv[j + 1], rowv[j + 2], rowv[j + 3]);
                if (bias) {
                    v.x += bias[c];     v.y += bias[c + 1];
                    v.z += bias[c + 2]; v.w += bias[c + 3];
                }
                if (relu) {
                    v.x = fmaxf(v.x, 0.f); v.y = fmaxf(v.y, 0.f);
                    v.z = fmaxf(v.z, 0.f); v.w = fmaxf(v.w, 0.f);
                }
                *reinterpret_cast<float4*>(C + (long)r * N + c) = v;
            }
        }
    }
}

// ---------------- head: out[n] = dot(relu_feats[n], w2) + b2 ----------------
__global__ void head_out_kernel(const float* __restrict__ T,
                                const float* __restrict__ w2,
                                const float* __restrict__ b2,
                                float* __restrict__ out, int n)
{
    int gw   = (blockIdx.x * blockDim.x + threadIdx.x) >> 5;
    int lane = threadIdx.x & 31;
    if (gw >= n) return;
    const float* t = T + (long)gw * HID;
    float acc = 0.f;
#pragma unroll
    for (int k = lane; k < HID; k += 32) acc = fmaf(t[k], w2[k], acc);
#pragma unroll
    for (int o = 16; o; o >>= 1) acc += __shfl_xor_sync(0xffffffffu, acc, o);
    if (lane == 0) out[gw] = acc + b2[0];
}

// ---------------- host orchestration ----------------
template <typename T>
static T* sym_addr(const void* symbol) {
    void* p = nullptr;
    cudaGetSymbolAddress(&p, symbol);
    return (T*)p;
}

static void run_gemm(const float* A1, const float* W1, int K1,
                     const float* A2, const float* W2, int K2,
                     const float* bias, int relu,
                     float* C, int M, int N, cudaStream_t s)
{
    dim3 grid(N / BN, (M + BM - 1) / BM);
    gemm_dual_kernel<<<grid, 256, 0, s>>>(A1, W1, K1, A2, W2, K2, bias, relu, C, M, N);
}

extern "C" void kernel_launch(void* const* d_in, const int* in_sizes, int n_in,
                              void* d_out, int out_size)
{
    cudaStream_t s = 0;
    const float* x     = (const float*)d_in[0];
    const int*   eidx  = (const int*)  d_in[1];
    const float* eattr = (const float*)d_in[2];
    const float* e0_w  = (const float*)d_in[3];
    const float* e0_b  = (const float*)d_in[4];
    const float* n0_w  = (const float*)d_in[5];
    const float* n0_b  = (const float*)d_in[6];
    const float* e_w   = (const float*)d_in[7];   // [2, 544, 256]
    const float* e_b   = (const float*)d_in[8];   // [2, 256]
    const float* n_w   = (const float*)d_in[9];   // [2, 512, 256]
    const float* n_b   = (const float*)d_in[10];  // [2, 256]
    const float* h1_w  = (const float*)d_in[11];
    const float* h1_b  = (const float*)d_in[12];
    const float* h2_w  = (const float*)d_in[13];
    const float* h2_b  = (const float*)d_in[14];

    const int* src = eidx;
    const int* dst = eidx + NE;

    float* Xs   = sym_addr<float>(g_Xs);
    float* Xd   = sym_addr<float>(g_Xd);
    float* agg  = sym_addr<float>(g_agg);
    float* h    = sym_addr<float>(g_h);
    float* h2   = sym_addr<float>(g_h2);
    float* Ea   = sym_addr<float>(g_Ea);
    int*   degi = sym_addr<int>(g_degi);
    int*   rowS = sym_addr<int>(g_rowstart);
    int*   curS = sym_addr<int>(g_cursor);
    int*   csrS = sym_addr<int>(g_csr_src);
    int*   csrE = sym_addr<int>(g_csr_eid);

    // ---------- CSR build (per launch, deterministic work) ----------
    zero_kernel<<<(NN / 4 + 255) / 256, 256, 0, s>>>((float*)degi, NN / 4);
    hist_kernel<<<(NE + 255) / 256, 256, 0, s>>>(dst, degi, NE);
    scan_kernel<<<1, 1024, 0, s>>>(degi, rowS, curS, NN);
    scatter_kernel<<<(NE + 255) / 256, 256, 0, s>>>(src, dst, curS, csrS, csrE, NE);

    // ---------- layer 0 (C = 128) ----------
    {
        const float* Ws = e0_w;
        const float* Wd = e0_w + (long)INC * HID;
        const float* We = e0_w + (long)2 * INC * HID;
        run_gemm(x, Ws, INC, nullptr, nullptr, 0, nullptr, 0, Xs, NN, HID, s);
        run_gemm(x, Wd, INC, nullptr, nullptr, 0, nullptr, 0, Xd, NN, HID, s);
        run_gemm(eattr, We, ED, nullptr, nullptr, 0, e0_b, 0, Ea, NE, HID, s);
        agg2_kernel<<<AGG_CTAS, 256, 0, s>>>(Xs, Xd, Ea, rowS, csrS, csrE, agg);
        run_gemm(x, n0_w, INC, agg, n0_w + (long)INC * HID, HID, n0_b, 1, h, NN, HID, s);
    }

    // ---------- layers 1..2 (C = 256) ----------
    float* cur = h;
    float* nxt = h2;
    for (int L = 0; L < 2; ++L) {
        const float* ew = e_w + (long)L * (2 * HID + ED) * HID;
        const float* eb = e_b + (long)L * HID;
        const float* nw = n_w + (long)L * (2 * HID) * HID;
        const float* nb = n_b + (long)L * HID;
        const float* Ws = ew;
        const float* Wd = ew + (long)HID * HID;
        const float* We = ew + (long)2 * HID * HID;

        run_gemm(cur, Ws, HID, nullptr, nullptr, 0, nullptr, 0, Xs, NN, HID, s);
        run_gemm(cur, Wd, HID, nullptr, nullptr, 0, nullptr, 0, Xd, NN, HID, s);
        run_gemm(eattr, We, ED, nullptr, nullptr, 0, eb, 0, Ea, NE, HID, s);
        agg2_kernel<<<AGG_CTAS, 256, 0, s>>>(Xs, Xd, Ea, rowS, csrS, csrE, agg);
        run_gemm(cur, nw, HID, agg, nw + (long)HID * HID, HID, nb, 1, nxt, NN, HID, s);

        float* t = cur; cur = nxt; nxt = t;
    }

    // ---------- head ----------
    run_gemm(cur, h1_w, HID, nullptr, nullptr, 0, h1_b, 1, nxt, NN, HID, s);
    head_out_kernel<<<(NN * 32 + 255) / 256, 256, 0, s>>>(nxt, h2_w, h2_b, (float*)d_out, NN);
}

// round 6
// speedup vs baseline: 2.2123x; 1.7339x over previous
#include <cuda_runtime.h>
#include <cuda_bf16.h>
#include <cstdint>

#define NN    50000
#define NE    400000
#define INC   128
#define HID   256
#define ED    32

// ---------------- scratch (static device buffers; no allocation) ----------------
__device__ float g_Xs [NN * HID];
__device__ float g_Xd [NN * HID];
__device__ float g_agg[NN * HID];
__device__ float g_h  [NN * HID];
__device__ float g_h2 [NN * HID];
__device__ float g_Ea [NE * HID];
__device__ int   g_degi[NN];
__device__ int   g_rowstart[NN + 1];
__device__ int   g_cursor[NN];
__device__ int   g_csr_src[NE];
__device__ int   g_csr_eid[NE];

// bf16 split buffers
__device__ __nv_bfloat16 g_xh[NN * INC], g_xl[NN * INC];
__device__ __nv_bfloat16 g_eah[NE * ED], g_eal[NE * ED];
__device__ __nv_bfloat16 g_ch[NN * HID], g_cl[NN * HID];
__device__ __nv_bfloat16 g_agh[NN * HID], g_agl[NN * HID];

// weight split scratch: e0_w(288*256) n0_w(384*256) e_w(2*544*256) n_w(2*512*256) h1_w(256*256)
#define OF_E0 0
#define OF_N0 73728
#define OF_EW 172032
#define OF_NW 450560
#define OF_H1 712704
#define WTOT  778240
__device__ __nv_bfloat16 g_wh[WTOT], g_wl[WTOT];

// ---------------- utility kernels ----------------
__global__ void zero_kernel(float* p, int n4) {
    int i = blockIdx.x * blockDim.x + threadIdx.x;
    if (i < n4) reinterpret_cast<float4*>(p)[i] = make_float4(0.f, 0.f, 0.f, 0.f);
}

__global__ void hist_kernel(const int* __restrict__ dst, int* degi, int E) {
    int e = blockIdx.x * blockDim.x + threadIdx.x;
    if (e < E) atomicAdd(&degi[dst[e]], 1);
}

__global__ void scan_kernel(const int* __restrict__ deg,
                            int* __restrict__ rowstart,
                            int* __restrict__ cursor, int n)
{
    __shared__ int wsum[32];
    __shared__ int woff[32];
    __shared__ int carry_s;
    __shared__ int tot_s;
    const int tid = threadIdx.x, lane = tid & 31, wid = tid >> 5;
    if (tid == 0) carry_s = 0;
    __syncthreads();

    for (int base = 0; base < n; base += 1024) {
        int i = base + tid;
        int v = (i < n) ? deg[i] : 0;
        int incl = v;
#pragma unroll
        for (int off = 1; off < 32; off <<= 1) {
            int t = __shfl_up_sync(0xffffffffu, incl, off);
            if (lane >= off) incl += t;
        }
        if (lane == 31) wsum[wid] = incl;
        __syncthreads();
        if (wid == 0) {
            int s = wsum[lane];
            int si = s;
#pragma unroll
            for (int off = 1; off < 32; off <<= 1) {
                int t = __shfl_up_sync(0xffffffffu, si, off);
                if (lane >= off) si += t;
            }
            woff[lane] = si - s;
            if (lane == 31) tot_s = si;
        }
        __syncthreads();
        int excl_all = carry_s + woff[wid] + (incl - v);
        if (i < n) { rowstart[i] = excl_all; cursor[i] = excl_all; }
        __syncthreads();
        if (tid == 0) carry_s += tot_s;
        __syncthreads();
    }
    if (tid == 0) rowstart[n] = carry_s;
}

__global__ void scatter_kernel(const int* __restrict__ src, const int* __restrict__ dst,
                               int* __restrict__ cursor,
                               int* __restrict__ csr_src, int* __restrict__ csr_eid, int E)
{
    int e = blockIdx.x * blockDim.x + threadIdx.x;
    if (e < E) {
        int d = dst[e];
        int pos = atomicAdd(&cursor[d], 1);
        csr_src[pos] = src[e];
        csr_eid[pos] = e;
    }
}

// ---------------- fp32 -> bf16 hi/lo split ----------------
__global__ void split_kernel(const float* __restrict__ src,
                             __nv_bfloat16* __restrict__ hi,
                             __nv_bfloat16* __restrict__ lo, int n4)
{
    int i = blockIdx.x * blockDim.x + threadIdx.x;
    if (i >= n4) return;
    float4 v = reinterpret_cast<const float4*>(src)[i];
    float vv[4] = {v.x, v.y, v.z, v.w};
    __nv_bfloat16 h[4], l[4];
#pragma unroll
    for (int j = 0; j < 4; j++) {
        h[j] = __float2bfloat16(vv[j]);
        l[j] = __float2bfloat16(vv[j] - __bfloat162float(h[j]));
    }
    reinterpret_cast<__nv_bfloat162*>(hi)[2 * i]     = __halves2bfloat162(h[0], h[1]);
    reinterpret_cast<__nv_bfloat162*>(hi)[2 * i + 1] = __halves2bfloat162(h[2], h[3]);
    reinterpret_cast<__nv_bfloat162*>(lo)[2 * i]     = __halves2bfloat162(l[0], l[1]);
    reinterpret_cast<__nv_bfloat162*>(lo)[2 * i + 1] = __halves2bfloat162(l[2], l[3]);
}

// ---------------- CSR mean aggregation (unchanged, streaming) ----------------
#define AGG_CTAS 1184

__global__ __launch_bounds__(256) void agg2_kernel(
    const float* __restrict__ Xs, const float* __restrict__ Xd,
    const float* __restrict__ Ea,
    const int* __restrict__ rowstart,
    const int* __restrict__ csr_src, const int* __restrict__ csr_eid,
    float* __restrict__ agg)
{
    const int j = threadIdx.x;
    for (int d = blockIdx.x; d < NN; d += gridDim.x) {
        const int rs = __ldg(&rowstart[d]);
        const int re = __ldg(&rowstart[d + 1]);
        const float xd = Xd[(long)d * HID + j];
        float acc0 = 0.f, acc1 = 0.f;
        int p = rs;
        for (; p + 1 < re; p += 2) {
            const int s0 = __ldg(&csr_src[p]);
            const int e0 = __ldg(&csr_eid[p]);
            const int s1 = __ldg(&csr_src[p + 1]);
            const int e1 = __ldg(&csr_eid[p + 1]);
            const float m0 = __ldg(&Xs[(long)s0 * HID + j]) + __ldg(&Ea[(long)e0 * HID + j]) + xd;
            const float m1 = __ldg(&Xs[(long)s1 * HID + j]) + __ldg(&Ea[(long)e1 * HID + j]) + xd;
            acc0 += fmaxf(m0, 0.f);
            acc1 += fmaxf(m1, 0.f);
        }
        if (p < re) {
            const int s0 = __ldg(&csr_src[p]);
            const int e0 = __ldg(&csr_eid[p]);
            acc0 += fmaxf(__ldg(&Xs[(long)s0 * HID + j]) + __ldg(&Ea[(long)e0 * HID + j]) + xd, 0.f);
        }
        const int  deg = re - rs;
        const float inv = 1.f / (float)((deg > 1) ? deg : 1);
        agg[(long)d * HID + j] = (acc0 + acc1) * inv;
    }
}

// ---------------- bf16 split tensor-core GEMM ----------------
// C = act( sum_seg A_seg @ W_seg + bias ), A [M,K] row-major bf16, W [K,N] row-major bf16.
// Segments implement both the 3-term precision split and the dual-input concat.
struct Segs {
    const __nv_bfloat16* A[6];
    const __nv_bfloat16* W[6];
    int K[6];
    int n;
};

#define GBM 128
#define GBN 128
#define GBK 32
#define ASTR 40    // GBK + 8 pad (bf16 units)
#define BSTR 136   // GBN + 8 pad

__device__ __forceinline__ void mma16816(float* c, const uint32_t* a, const uint32_t* b) {
    asm volatile(
        "mma.sync.aligned.m16n8k16.row.col.f32.bf16.bf16.f32 "
        "{%0,%1,%2,%3}, {%4,%5,%6,%7}, {%8,%9}, {%0,%1,%2,%3};"
        : "+f"(c[0]), "+f"(c[1]), "+f"(c[2]), "+f"(c[3])
        : "r"(a[0]), "r"(a[1]), "r"(a[2]), "r"(a[3]), "r"(b[0]), "r"(b[1]));
}

__global__ __launch_bounds__(256, 2) void bgemm_kernel(
    Segs S, const float* __restrict__ bias, int relu,
    float* __restrict__ C, int M, int N)
{
    __shared__ __nv_bfloat16 sA[2][GBM * ASTR];
    __shared__ __nv_bfloat16 sB[2][GBK * BSTR];

    const int tid  = threadIdx.x;
    const int bm   = blockIdx.y * GBM;
    const int bn   = blockIdx.x * GBN;
    const int wid  = tid >> 5, lane = tid & 31;
    const int wm   = wid & 3, wn = wid >> 2;   // 4 x 2 warp grid; warp tile 32x64

    float acc[2][8][4];
#pragma unroll
    for (int i = 0; i < 2; i++)
#pragma unroll
        for (int j = 0; j < 8; j++)
#pragma unroll
            for (int q = 0; q < 4; q++) acc[i][j][q] = 0.f;

    int total = 0;
#pragma unroll
    for (int i = 0; i < 6; i++) if (i < S.n) total += S.K[i] / GBK;

    auto load_tile = [&](int seg, int k0, int st) {
        const __nv_bfloat16* A = S.A[seg];
        const __nv_bfloat16* W = S.W[seg];
        const int K = S.K[seg];
#pragma unroll
        for (int t = 0; t < 2; t++) {
            int c = tid + t * 256;
            int row = c >> 2, sg = c & 3;
            int r = bm + row;
            int valid = (r < M);
            const __nv_bfloat16* src = A + (long)(valid ? r : 0) * K + k0 + sg * 8;
            uint32_t dst = (uint32_t)__cvta_generic_to_shared(&sA[st][row * ASTR + sg * 8]);
            int sz = valid ? 16 : 0;
            asm volatile("cp.async.cg.shared.global [%0], [%1], 16, %2;\n"
                         :: "r"(dst), "l"(src), "r"(sz));
        }
#pragma unroll
        for (int t = 0; t < 2; t++) {
            int c = tid + t * 256;
            int row = c >> 4, sg = c & 15;
            const __nv_bfloat16* src = W + (long)(k0 + row) * N + bn + sg * 8;
            uint32_t dst = (uint32_t)__cvta_generic_to_shared(&sB[st][row * BSTR + sg * 8]);
            asm volatile("cp.async.cg.shared.global [%0], [%1], 16;\n"
                         :: "r"(dst), "l"(src));
        }
    };

    auto compute = [&](int st) {
#pragma unroll
        for (int kk = 0; kk < GBK; kk += 16) {
            uint32_t af[2][4];
#pragma unroll
            for (int mi = 0; mi < 2; mi++) {
                int row = wm * 32 + mi * 16 + (lane & 15);
                int col = kk + (lane >> 4) * 8;
                uint32_t addr = (uint32_t)__cvta_generic_to_shared(&sA[st][row * ASTR + col]);
                asm volatile("ldmatrix.sync.aligned.m8n8.x4.shared.b16 {%0,%1,%2,%3}, [%4];"
                             : "=r"(af[mi][0]), "=r"(af[mi][1]), "=r"(af[mi][2]), "=r"(af[mi][3])
                             : "r"(addr));
            }
            uint32_t bfr[4][4];
#pragma unroll
            for (int nj = 0; nj < 4; nj++) {
                int row = kk + (lane & 7) + ((lane >> 3) & 1) * 8;
                int col = wn * 64 + nj * 16 + (lane >> 4) * 8;
                uint32_t addr = (uint32_t)__cvta_generic_to_shared(&sB[st][row * BSTR + col]);
                asm volatile("ldmatrix.sync.aligned.m8n8.x4.trans.shared.b16 {%0,%1,%2,%3}, [%4];"
                             : "=r"(bfr[nj][0]), "=r"(bfr[nj][1]), "=r"(bfr[nj][2]), "=r"(bfr[nj][3])
                             : "r"(addr));
            }
#pragma unroll
            for (int mi = 0; mi < 2; mi++)
#pragma unroll
                for (int nj = 0; nj < 8; nj++) {
                    const uint32_t* b = (nj & 1) ? &bfr[nj >> 1][2] : &bfr[nj >> 1][0];
                    mma16816(acc[mi][nj], af[mi], b);
                }
        }
    };

    int seg = 0, k0 = 0;
    load_tile(0, 0, 0);
    asm volatile("cp.async.commit_group;\n");

    for (int t = 0; t < total; ++t) {
        int ns = seg, nk = k0 + GBK;
        if (nk >= S.K[ns]) { ns++; nk = 0; }
        if (t + 1 < total) {
            load_tile(ns, nk, (t + 1) & 1);
            asm volatile("cp.async.commit_group;\n");
            asm volatile("cp.async.wait_group 1;\n");
        } else {
            asm volatile("cp.async.wait_group 0;\n");
        }
        __syncthreads();
        compute(t & 1);
        __syncthreads();
        seg = ns; k0 = nk;
    }

    // epilogue
#pragma unroll
    for (int mi = 0; mi < 2; mi++) {
        int r0 = bm + wm * 32 + mi * 16 + (lane >> 2);
#pragma unroll
        for (int nj = 0; nj < 8; nj++) {
            int c = bn + wn * 64 + nj * 8 + (lane & 3) * 2;
            float b0 = 0.f, b1 = 0.f;
            if (bias) { b0 = bias[c]; b1 = bias[c + 1]; }
            float v0 = acc[mi][nj][0] + b0, v1 = acc[mi][nj][1] + b1;
            float v2 = acc[mi][nj][2] + b0, v3 = acc[mi][nj][3] + b1;
            if (relu) {
                v0 = fmaxf(v0, 0.f); v1 = fmaxf(v1, 0.f);
                v2 = fmaxf(v2, 0.f); v3 = fmaxf(v3, 0.f);
            }
            if (r0 < M)     *reinterpret_cast<float2*>(C + (long)r0 * N + c)       = make_float2(v0, v1);
            if (r0 + 8 < M) *reinterpret_cast<float2*>(C + (long)(r0 + 8) * N + c) = make_float2(v2, v3);
        }
    }
}

// ---------------- head: out[n] = dot(relu_feats[n], w2) + b2 ----------------
__global__ void head_out_kernel(const float* __restrict__ T,
                                const float* __restrict__ w2,
                                const float* __restrict__ b2,
                                float* __restrict__ out, int n)
{
    int gw   = (blockIdx.x * blockDim.x + threadIdx.x) >> 5;
    int lane = threadIdx.x & 31;
    if (gw >= n) return;
    const float* t = T + (long)gw * HID;
    float acc = 0.f;
#pragma unroll
    for (int k = lane; k < HID; k += 32) acc = fmaf(t[k], w2[k], acc);
#pragma unroll
    for (int o = 16; o; o >>= 1) acc += __shfl_xor_sync(0xffffffffu, acc, o);
    if (lane == 0) out[gw] = acc + b2[0];
}

// ---------------- host orchestration ----------------
template <typename T>
static T* sym_addr(const void* symbol) {
    void* p = nullptr;
    cudaGetSymbolAddress(&p, symbol);
    return (T*)p;
}

typedef const __nv_bfloat16* bfp;

static void seg3(Segs& S, bfp Ah, bfp Al, bfp Wh, bfp Wl, int K) {
    int i = S.n;
    S.A[i] = Ah; S.W[i] = Wh; S.K[i] = K; i++;
    S.A[i] = Ah; S.W[i] = Wl; S.K[i] = K; i++;
    S.A[i] = Al; S.W[i] = Wh; S.K[i] = K; i++;
    S.n = i;
}

static void run_bgemm(const Segs& S, const float* bias, int relu,
                      float* C, int M, int N, cudaStream_t s)
{
    dim3 grid(N / GBN, (M + GBM - 1) / GBM);
    bgemm_kernel<<<grid, 256, 0, s>>>(S, bias, relu, C, M, N);
}

static void run_split(const float* src, __nv_bfloat16* hi, __nv_bfloat16* lo,
                      int n, cudaStream_t s)
{
    int n4 = n / 4;
    split_kernel<<<(n4 + 255) / 256, 256, 0, s>>>(src, hi, lo, n4);
}

extern "C" void kernel_launch(void* const* d_in, const int* in_sizes, int n_in,
                              void* d_out, int out_size)
{
    cudaStream_t s = 0;
    const float* x     = (const float*)d_in[0];
    const int*   eidx  = (const int*)  d_in[1];
    const float* eattr = (const float*)d_in[2];
    const float* e0_w  = (const float*)d_in[3];
    const float* e0_b  = (const float*)d_in[4];
    const float* n0_w  = (const float*)d_in[5];
    const float* n0_b  = (const float*)d_in[6];
    const float* e_w   = (const float*)d_in[7];
    const float* e_b   = (const float*)d_in[8];
    const float* n_w   = (const float*)d_in[9];
    const float* n_b   = (const float*)d_in[10];
    const float* h1_w  = (const float*)d_in[11];
    const float* h1_b  = (const float*)d_in[12];
    const float* h2_w  = (const float*)d_in[13];
    const float* h2_b  = (const float*)d_in[14];

    const int* src = eidx;
    const int* dst = eidx + NE;

    float* Xs   = sym_addr<float>(g_Xs);
    float* Xd   = sym_addr<float>(g_Xd);
    float* agg  = sym_addr<float>(g_agg);
    float* h    = sym_addr<float>(g_h);
    float* h2   = sym_addr<float>(g_h2);
    float* Ea   = sym_addr<float>(g_Ea);
    int*   degi = sym_addr<int>(g_degi);
    int*   rowS = sym_addr<int>(g_rowstart);
    int*   curS = sym_addr<int>(g_cursor);
    int*   csrS = sym_addr<int>(g_csr_src);
    int*   csrE = sym_addr<int>(g_csr_eid);

    __nv_bfloat16* xh  = sym_addr<__nv_bfloat16>(g_xh);
    __nv_bfloat16* xl  = sym_addr<__nv_bfloat16>(g_xl);
    __nv_bfloat16* eah = sym_addr<__nv_bfloat16>(g_eah);
    __nv_bfloat16* eal = sym_addr<__nv_bfloat16>(g_eal);
    __nv_bfloat16* ch  = sym_addr<__nv_bfloat16>(g_ch);
    __nv_bfloat16* cl  = sym_addr<__nv_bfloat16>(g_cl);
    __nv_bfloat16* agh = sym_addr<__nv_bfloat16>(g_agh);
    __nv_bfloat16* agl = sym_addr<__nv_bfloat16>(g_agl);
    __nv_bfloat16* wh  = sym_addr<__nv_bfloat16>(g_wh);
    __nv_bfloat16* wl  = sym_addr<__nv_bfloat16>(g_wl);

    // ---------- splits (weights + static inputs) ----------
    run_split(e0_w, wh + OF_E0, wl + OF_E0, 288 * 256, s);
    run_split(n0_w, wh + OF_N0, wl + OF_N0, 384 * 256, s);
    run_split(e_w,  wh + OF_EW, wl + OF_EW, 2 * 544 * 256, s);
    run_split(n_w,  wh + OF_NW, wl + OF_NW, 2 * 512 * 256, s);
    run_split(h1_w, wh + OF_H1, wl + OF_H1, 256 * 256, s);
    run_split(x,     xh,  xl,  NN * INC, s);
    run_split(eattr, eah, eal, NE * ED, s);

    // ---------- CSR build ----------
    zero_kernel<<<(NN / 4 + 255) / 256, 256, 0, s>>>((float*)degi, NN / 4);
    hist_kernel<<<(NE + 255) / 256, 256, 0, s>>>(dst, degi, NE);
    scan_kernel<<<1, 1024, 0, s>>>(degi, rowS, curS, NN);
    scatter_kernel<<<(NE + 255) / 256, 256, 0, s>>>(src, dst, curS, csrS, csrE, NE);

    // ---------- layer 0 (C = 128) ----------
    {
        bfp Wsh = wh + OF_E0,             Wsl = wl + OF_E0;
        bfp Wdh = wh + OF_E0 + 128 * 256, Wdl = wl + OF_E0 + 128 * 256;
        bfp Weh = wh + OF_E0 + 256 * 256, Wel = wl + OF_E0 + 256 * 256;

        Segs S1 = {}; seg3(S1, xh, xl, Wsh, Wsl, INC);
        run_bgemm(S1, nullptr, 0, Xs, NN, HID, s);
        Segs S2 = {}; seg3(S2, xh, xl, Wdh, Wdl, INC);
        run_bgemm(S2, nullptr, 0, Xd, NN, HID, s);
        Segs S3 = {}; seg3(S3, eah, eal, Weh, Wel, ED);
        run_bgemm(S3, e0_b, 0, Ea, NE, HID, s);

        agg2_kernel<<<AGG_CTAS, 256, 0, s>>>(Xs, Xd, Ea, rowS, csrS, csrE, agg);
        run_split(agg, agh, agl, NN * HID, s);

        Segs S4 = {};
        seg3(S4, xh, xl, wh + OF_N0, wl + OF_N0, INC);
        seg3(S4, agh, agl, wh + OF_N0 + 128 * 256, wl + OF_N0 + 128 * 256, HID);
        run_bgemm(S4, n0_b, 1, h, NN, HID, s);
    }

    // ---------- layers 1..2 (C = 256) ----------
    float* cur = h;
    float* nxt = h2;
    for (int L = 0; L < 2; ++L) {
        bfp ewh = wh + OF_EW + (long)L * 544 * 256;
        bfp ewl = wl + OF_EW + (long)L * 544 * 256;
        bfp nwh = wh + OF_NW + (long)L * 512 * 256;
        bfp nwl = wl + OF_NW + (long)L * 512 * 256;
        const float* eb = e_b + (long)L * HID;
        const float* nb = n_b + (long)L * HID;

        run_split(cur, ch, cl, NN * HID, s);

        Segs S1 = {}; seg3(S1, ch, cl, ewh, ewl, HID);
        run_bgemm(S1, nullptr, 0, Xs, NN, HID, s);
        Segs S2 = {}; seg3(S2, ch, cl, ewh + 256 * 256, ewl + 256 * 256, HID);
        run_bgemm(S2, nullptr, 0, Xd, NN, HID, s);
        Segs S3 = {}; seg3(S3, eah, eal, ewh + 512 * 256, ewl + 512 * 256, ED);
        run_bgemm(S3, eb, 0, Ea, NE, HID, s);

        agg2_kernel<<<AGG_CTAS, 256, 0, s>>>(Xs, Xd, Ea, rowS, csrS, csrE, agg);
        run_split(agg, agh, agl, NN * HID, s);

        Segs S4 = {};
        seg3(S4, ch, cl, nwh, nwl, HID);
        seg3(S4, agh, agl, nwh + 256 * 256, nwl + 256 * 256, HID);
        run_bgemm(S4, nb, 1, nxt, NN, HID, s);

        float* t = cur; cur = nxt; nxt = t;
    }

    // ---------- head ----------
    run_split(cur, ch, cl, NN * HID, s);
    Segs SH = {}; seg3(SH, ch, cl, wh + OF_H1, wl + OF_H1, HID);
    run_bgemm(SH, h1_b, 1, nxt, NN, HID, s);
    head_out_kernel<<<(NN * 32 + 255) / 256, 256, 0, s>>>(nxt, h2_w, h2_b, (float*)d_out, NN);
}